// round 9
// baseline (speedup 1.0000x reference)
#include <cuda_runtime.h>
#include <cstdint>

// MemoryReader attention: SIMT fp32 logits/softmax + HMMA (mma.sync tf32) readout.
//   B=16, CK=64, CV=512, N=3136, 64 queries/CTA, 64-key tiles.
// Round 6: E stored transposed [q][k] pitch 68 -> B-fragment LDS conflict-free
// (was 4-way conflicted in [k][q] layout, the dominant smem-wavefront term).
// Denominator now accumulated via register partials + spread smem atomics.

#define Bsz     16
#define CKc     64
#define CVc     512
#define NPIX    3136
#define MQ      64
#define NT      64
#define THREADS 512
#define NTILES  (NPIX / NT)   // 49
#define PITCH   68            // V tile pitch (words): conflict-free frag LDS
#define EPITCH  68            // Et tile pitch (words): conflict-free B-frag LDS

typedef unsigned long long u64;

__device__ __forceinline__ uint32_t cvt_tf32(float f) {
    uint32_t r; asm("cvt.rna.tf32.f32 %0, %1;" : "=r"(r) : "f"(f)); return r;
}
__device__ __forceinline__ u64 pack2(float lo, float hi) {
    u64 r; asm("mov.b64 %0, {%1, %2};" : "=l"(r) : "f"(lo), "f"(hi)); return r;
}
__device__ __forceinline__ void unpack2(u64 v, float& lo, float& hi) {
    asm("mov.b64 {%0, %1}, %2;" : "=f"(lo), "=f"(hi) : "l"(v));
}
__device__ __forceinline__ u64 fma2(u64 a, u64 b, u64 c) {
    u64 d; asm("fma.rn.f32x2 %0, %1, %2, %3;" : "=l"(d) : "l"(a), "l"(b), "l"(c)); return d;
}
__device__ __forceinline__ void mma_tf32(float d[4], const uint32_t a[4], const uint32_t b[2]) {
    asm volatile(
        "mma.sync.aligned.m16n8k8.row.col.f32.tf32.tf32.f32 "
        "{%0,%1,%2,%3}, {%4,%5,%6,%7}, {%8,%9}, {%0,%1,%2,%3};"
        : "+f"(d[0]), "+f"(d[1]), "+f"(d[2]), "+f"(d[3])
        : "r"(a[0]), "r"(a[1]), "r"(a[2]), "r"(a[3]), "r"(b[0]), "r"(b[1]));
}

__global__ __launch_bounds__(THREADS, 1)
void mr_attn_kernel(const float* __restrict__ mk, const float* __restrict__ qk,
                    const float* __restrict__ mv, float* __restrict__ out)
{
    extern __shared__ float sm[];
    float* Qs = sm;                      // [64ck][64q]     4096 w (fp32)
    float* Ks = Qs + CKc * MQ;           // [64ck][64key]   4096 w (fp32)
    float* Et = Ks + CKc * NT;           // [64q][EPITCH]   4352 w (tf32 bits, TRANSPOSED)
    float* Vs = Et + MQ * EPITCH;        // [512ch][PITCH]  34816 w (tf32 bits)
    float* S2 = Vs + CVc * PITCH;        // [64]
    float* Dn = S2 + NT;                 // [64]

    const int b    = blockIdx.y;
    const int m0   = blockIdx.x * MQ;
    const int tid  = threadIdx.x;
    const int wid  = tid >> 5;
    const int lane = tid & 31;
    const int g    = lane >> 2;          // mma group row
    const int tq   = lane & 3;           // mma quad col

    const float* qb = qk + (size_t)b * CKc * NPIX + m0;
    const float* kb = mk + (size_t)b * CKc * NPIX;
    const float* vb = mv + (size_t)b * CVc * NPIX;

    // Q tile (fp32, SIMT logits)
    #pragma unroll
    for (int idx = tid; idx < CKc * (MQ / 4); idx += THREADS) {
        int c = idx >> 4, m4 = idx & 15;
        *(float4*)(Qs + c * MQ + 4 * m4) = *(const float4*)(qb + c * NPIX + 4 * m4);
    }
    if (tid < MQ) Dn[tid] = 0.f;

    // Accumulator fragments: 2 m-tiles (16ch) x 8 n-tiles (8q), 4 regs each
    float d[2][8][4];
    #pragma unroll
    for (int i = 0; i < 2; ++i)
        #pragma unroll
        for (int j = 0; j < 8; ++j)
            #pragma unroll
            for (int r = 0; r < 4; ++r) d[i][j][r] = 0.f;

    const int ch0 = wid * 32;            // warp's channel slab
    const int ln  = wid * 4;             // logits: 4 keys per thread
    const int lm  = lane * 2;            // logits: 2 queries per thread

    for (int t = 0; t < NTILES; ++t) {
        const int n0 = t * NT;
        __syncthreads();   // previous tile's frag reads done; tiles reusable

        // K tile (fp32 for logits)
        #pragma unroll
        for (int idx = tid; idx < CKc * (NT / 4); idx += THREADS) {
            int c = idx >> 4, n4 = idx & 15;
            *(float4*)(Ks + c * NT + 4 * n4) = *(const float4*)(kb + c * NPIX + n0 + 4 * n4);
        }
        // V tile -> tf32 bits, natural c-major layout, pitch 68
        #pragma unroll
        for (int idx = tid; idx < CVc * (NT / 4); idx += THREADS) {
            int c = idx >> 4, n4 = idx & 15;
            float4 v = *(const float4*)(vb + c * NPIX + n0 + 4 * n4);
            uint4 tv = make_uint4(cvt_tf32(v.x), cvt_tf32(v.y), cvt_tf32(v.z), cvt_tf32(v.w));
            *(uint4*)(Vs + c * PITCH + 4 * n4) = tv;
        }
        __syncthreads();

        // ||k||^2 per key
        if (tid < NT) {
            float s = 0.f;
            #pragma unroll
            for (int c = 0; c < CKc; ++c) { float k = Ks[c * NT + tid]; s = fmaf(k, k, s); }
            S2[tid] = s;
        }
        __syncthreads();

        // Logits + exp (fp32 FFMA2): 4 keys x 2 queries/thread; Et[q][k] <- tf32
        {
            u64 dot2[4] = {0ull, 0ull, 0ull, 0ull};
            #pragma unroll
            for (int c = 0; c < CKc; ++c) {
                float4 k4 = *(const float4*)(Ks + c * NT + ln);
                u64 qp = *(const u64*)(Qs + c * MQ + lm);
                dot2[0] = fma2(pack2(k4.x, k4.x), qp, dot2[0]);
                dot2[1] = fma2(pack2(k4.y, k4.y), qp, dot2[1]);
                dot2[2] = fma2(pack2(k4.z, k4.z), qp, dot2[2]);
                dot2[3] = fma2(pack2(k4.w, k4.w), qp, dot2[3]);
            }
            const float C1 = 0.125f * 1.4426950408889634f;  // log2(e)/sqrt(CK)
            float4 s4 = *(const float4*)(S2 + ln);
            float sb[4] = {s4.x * C1, s4.y * C1, s4.z * C1, s4.w * C1};
            float p0 = 0.f, p1 = 0.f;
            #pragma unroll
            for (int i = 0; i < 4; ++i) {
                float d0, d1; unpack2(dot2[i], d0, d1);
                float e0 = exp2f(fmaf(d0, 2.f * C1, -sb[i]));
                float e1 = exp2f(fmaf(d1, 2.f * C1, -sb[i]));
                p0 += e0; p1 += e1;
                Et[lm * EPITCH + ln + i]       = __uint_as_float(cvt_tf32(e0));
                Et[(lm + 1) * EPITCH + ln + i] = __uint_as_float(cvt_tf32(e1));
            }
            // denominator: register partials, spread smem atomics (distinct addr/warp)
            atomicAdd(&Dn[lm],     p0);
            atomicAdd(&Dn[lm + 1], p1);
        }
        __syncthreads();

        // Readout: D[32ch x 64q] += V[32ch x 64k] * E[64k x 64q] via HMMA tf32
        // A-frag banks: (4g+tq) bijective -> conflict-free.
        // B-frag banks: Et[(j*8+g)*68 + k0+tq] -> (4g+tq+k0)%32 -> conflict-free.
        const uint32_t* Vu = (const uint32_t*)Vs;
        const uint32_t* Eu = (const uint32_t*)Et;
        #pragma unroll
        for (int s = 0; s < 8; ++s) {               // k-step of 8
            const int k0 = s * 8;
            uint32_t a[2][4];
            #pragma unroll
            for (int i = 0; i < 2; ++i) {
                int row = ch0 + 16 * i + g;
                a[i][0] = Vu[row * PITCH + k0 + tq];
                a[i][1] = Vu[(row + 8) * PITCH + k0 + tq];
                a[i][2] = Vu[row * PITCH + k0 + tq + 4];
                a[i][3] = Vu[(row + 8) * PITCH + k0 + tq + 4];
            }
            uint32_t bfr[8][2];
            #pragma unroll
            for (int j = 0; j < 8; ++j) {
                int q = j * 8 + g;
                bfr[j][0] = Eu[q * EPITCH + k0 + tq];
                bfr[j][1] = Eu[q * EPITCH + k0 + tq + 4];
            }
            #pragma unroll
            for (int i = 0; i < 2; ++i)
                #pragma unroll
                for (int j = 0; j < 8; ++j)
                    mma_tf32(d[i][j], a[i], bfr[j]);
        }
    }
    __syncthreads();
    if (tid < MQ) Dn[tid] = 1.0f / Dn[tid];
    __syncthreads();

    // Epilogue: scale by 1/denominator, store
    #pragma unroll
    for (int i = 0; i < 2; ++i) {
        int ch = ch0 + 16 * i + g;
        float* op0 = out + ((size_t)b * CVc + ch) * NPIX + m0;
        float* op1 = out + ((size_t)b * CVc + ch + 8) * NPIX + m0;
        #pragma unroll
        for (int j = 0; j < 8; ++j) {
            int q = j * 8 + 2 * tq;
            float2 dn2 = *(const float2*)(Dn + q);
            float2 o0 = make_float2(d[i][j][0] * dn2.x, d[i][j][1] * dn2.y);
            float2 o1 = make_float2(d[i][j][2] * dn2.x, d[i][j][3] * dn2.y);
            *(float2*)(op0 + q) = o0;
            *(float2*)(op1 + q) = o1;
        }
    }
}

extern "C" void kernel_launch(void* const* d_in, const int* in_sizes, int n_in,
                              void* d_out, int out_size)
{
    const float* mk = (const float*)d_in[0];
    const float* qk = (const float*)d_in[1];
    const float* mv = (const float*)d_in[2];
    const float* qv = (const float*)d_in[3];
    float* out = (float*)d_out;

    size_t smem = (size_t)(CKc * MQ + CKc * NT + MQ * EPITCH + CVc * PITCH + NT + MQ)
                  * sizeof(float);
    cudaFuncSetAttribute(mr_attn_kernel, cudaFuncAttributeMaxDynamicSharedMemorySize, (int)smem);

    dim3 grid(NPIX / MQ, Bsz);   // 49 x 16
    mr_attn_kernel<<<grid, THREADS, smem>>>(mk, qk, mv, out);

    size_t memElems = (size_t)Bsz * CVc * NPIX;
    if ((size_t)out_size >= 2 * memElems) {
        cudaMemcpyAsync(out + memElems, qv, memElems * sizeof(float),
                        cudaMemcpyDeviceToDevice);
    }
}

// round 10
// speedup vs baseline: 1.1345x; 1.1345x over previous
#include <cuda_runtime.h>
#include <cstdint>

// MemoryReader attention — both GEMMs on tensor pipe (mma.sync tf32).
//   B=16, CK=64, CV=512, N=3136, 64 queries/CTA, 64-key tiles.
// R10: logits moved from FFMA2 to MMA with 3xTF32 split (hi/lo of Q and K,
// hh+hl+lh) -> logit error ~1e-5, total rel_err stays ~2.9e-4 (V/E rounding).
// Qt (hi/lo) built once per CTA; K stays natural c-major (no per-tile transpose).
// All frag/STS patterns bank-conflict-free (Qt p68: 4g+tq, Ks p72: 8tq+g,
// V/Et p68: 4g+tq bijective).

#define Bsz     16
#define CKc     64
#define CVc     512
#define NPIX    3136
#define MQ      64
#define NT      64
#define THREADS 512
#define NTILES  (NPIX / NT)   // 49

#define QTP 68   // Qt pitch
#define KSP 72   // Ks pitch
#define ETP 68   // Et pitch
#define VP  68   // Vs pitch

// smem word offsets
#define QTH_OFF 0                      // [64q][QTP]
#define QTL_OFF (QTH_OFF + MQ * QTP)   // 4352
#define KSH_OFF (QTL_OFF + MQ * QTP)   // 8704  [64c][KSP]
#define KSL_OFF (KSH_OFF + CKc * KSP)  // 13312
#define ET_OFF  (KSL_OFF + CKc * KSP)  // 17920 [64q][ETP]
#define VS_OFF  (ET_OFF + MQ * ETP)    // 22272 [512ch][VP]
#define S2_OFF  (VS_OFF + CVc * VP)    // 57088
#define DN_OFF  (S2_OFF + NT)          // 57152
#define SMEM_W  (DN_OFF + MQ)          // 57216 words = 228864 B

__device__ __forceinline__ float tf32r(float x) {
    uint32_t u; asm("cvt.rna.tf32.f32 %0, %1;" : "=r"(u) : "f"(x));
    return __uint_as_float(u);
}
__device__ __forceinline__ void mma_tf32(float d[4], const uint32_t a[4], const uint32_t b[2]) {
    asm volatile(
        "mma.sync.aligned.m16n8k8.row.col.f32.tf32.tf32.f32 "
        "{%0,%1,%2,%3}, {%4,%5,%6,%7}, {%8,%9}, {%0,%1,%2,%3};"
        : "+f"(d[0]), "+f"(d[1]), "+f"(d[2]), "+f"(d[3])
        : "r"(a[0]), "r"(a[1]), "r"(a[2]), "r"(a[3]), "r"(b[0]), "r"(b[1]));
}

__global__ __launch_bounds__(THREADS, 1)
void mr_attn_kernel(const float* __restrict__ mk, const float* __restrict__ qk,
                    const float* __restrict__ mv, float* __restrict__ out)
{
    extern __shared__ float sm[];
    float* Qth = sm + QTH_OFF;
    float* Qtl = sm + QTL_OFF;
    float* Ksh = sm + KSH_OFF;
    float* Ksl = sm + KSL_OFF;
    float* Et  = sm + ET_OFF;
    float* Vs  = sm + VS_OFF;
    float* S2  = sm + S2_OFF;
    float* Dn  = sm + DN_OFF;

    const int b    = blockIdx.y;
    const int m0   = blockIdx.x * MQ;
    const int tid  = threadIdx.x;
    const int wid  = tid >> 5;
    const int lane = tid & 31;
    const int g    = lane >> 2;
    const int tq   = lane & 3;

    const float* qb = qk + (size_t)b * CKc * NPIX + m0;
    const float* kb = mk + (size_t)b * CKc * NPIX;
    const float* vb = mv + (size_t)b * CVc * NPIX;

    // Build Qt hi/lo ONCE (transpose; conflicted STS but amortized over 49 tiles)
    #pragma unroll
    for (int idx = tid; idx < CKc * (MQ / 4); idx += THREADS) {
        int c = idx >> 4, m4 = idx & 15;
        float4 v = *(const float4*)(qb + c * NPIX + 4 * m4);
        float vv[4] = {v.x, v.y, v.z, v.w};
        #pragma unroll
        for (int r = 0; r < 4; ++r) {
            float hi = tf32r(vv[r]);
            Qth[(4 * m4 + r) * QTP + c] = hi;
            Qtl[(4 * m4 + r) * QTP + c] = tf32r(vv[r] - hi);
        }
    }
    if (tid < MQ) Dn[tid] = 0.f;

    // Readout accumulators: warp slab 32ch x 64q
    float d[2][8][4];
    #pragma unroll
    for (int i = 0; i < 2; ++i)
        #pragma unroll
        for (int j = 0; j < 8; ++j)
            #pragma unroll
            for (int r = 0; r < 4; ++r) d[i][j][r] = 0.f;

    const int ch0 = wid * 32;        // readout channel slab
    const int wq  = wid & 3;         // logit q m-tile (16q)
    const int wk  = wid >> 2;        // logit k n-pair (16k)
    const int q0  = wq * 16;

    for (int t = 0; t < NTILES; ++t) {
        const int n0 = t * NT;
        __syncthreads();   // previous readout done; tiles reusable

        // K tile -> hi/lo tf32, natural c-major, pitch 72 (coalesced, cf STS.128)
        #pragma unroll
        for (int idx = tid; idx < CKc * (NT / 4); idx += THREADS) {
            int c = idx >> 4, n4 = idx & 15;
            float4 v = *(const float4*)(kb + c * NPIX + n0 + 4 * n4);
            float4 hi = make_float4(tf32r(v.x), tf32r(v.y), tf32r(v.z), tf32r(v.w));
            float4 lo = make_float4(tf32r(v.x - hi.x), tf32r(v.y - hi.y),
                                    tf32r(v.z - hi.z), tf32r(v.w - hi.w));
            *(float4*)(Ksh + c * KSP + 4 * n4) = hi;
            *(float4*)(Ksl + c * KSP + 4 * n4) = lo;
        }
        // V tile -> tf32, natural c-major, pitch 68
        #pragma unroll
        for (int idx = tid; idx < CVc * (NT / 4); idx += THREADS) {
            int c = idx >> 4, n4 = idx & 15;
            float4 v = *(const float4*)(vb + c * NPIX + n0 + 4 * n4);
            float4 tv = make_float4(tf32r(v.x), tf32r(v.y), tf32r(v.z), tf32r(v.w));
            *(float4*)(Vs + c * VP + 4 * n4) = tv;
        }
        __syncthreads();

        // ||k||^2 (hi+lo == exact fp32 K); banks (8c+k) conflict-free
        if (tid < NT) {
            float s = 0.f;
            #pragma unroll
            for (int c = 0; c < CKc; ++c) {
                float k = Ksh[c * KSP + tid] + Ksl[c * KSP + tid];
                s = fmaf(k, k, s);
            }
            S2[tid] = s;
        }

        // Logit MMA: Dl[q,k] = Qt * K, 3xTF32 (hh + hl + lh)
        float dl[2][4] = {{0.f, 0.f, 0.f, 0.f}, {0.f, 0.f, 0.f, 0.f}};
        {
            const uint32_t* Qhu = (const uint32_t*)Qth;
            const uint32_t* Qlu = (const uint32_t*)Qtl;
            const uint32_t* Khu = (const uint32_t*)Ksh;
            const uint32_t* Klu = (const uint32_t*)Ksl;
            #pragma unroll
            for (int cs = 0; cs < 8; ++cs) {
                const int c0 = cs * 8;
                uint32_t ah[4], al[4];
                ah[0] = Qhu[(q0 + g) * QTP + c0 + tq];
                ah[1] = Qhu[(q0 + g + 8) * QTP + c0 + tq];
                ah[2] = Qhu[(q0 + g) * QTP + c0 + tq + 4];
                ah[3] = Qhu[(q0 + g + 8) * QTP + c0 + tq + 4];
                al[0] = Qlu[(q0 + g) * QTP + c0 + tq];
                al[1] = Qlu[(q0 + g + 8) * QTP + c0 + tq];
                al[2] = Qlu[(q0 + g) * QTP + c0 + tq + 4];
                al[3] = Qlu[(q0 + g + 8) * QTP + c0 + tq + 4];
                #pragma unroll
                for (int j = 0; j < 2; ++j) {
                    const int k0 = wk * 16 + 8 * j;
                    uint32_t bh[2], bl[2];
                    bh[0] = Khu[(c0 + tq) * KSP + k0 + g];
                    bh[1] = Khu[(c0 + tq + 4) * KSP + k0 + g];
                    bl[0] = Klu[(c0 + tq) * KSP + k0 + g];
                    bl[1] = Klu[(c0 + tq + 4) * KSP + k0 + g];
                    mma_tf32(dl[j], ah, bh);
                    mma_tf32(dl[j], ah, bl);
                    mma_tf32(dl[j], al, bh);
                }
            }
        }
        __syncthreads();   // S2 visible to all

        // exp + Et[q][k] store (tf32 bits) + denominator
        {
            const float C1 = 0.125f * 1.4426950408889634f;   // log2(e)/8
            float pA = 0.f, pB = 0.f;
            #pragma unroll
            for (int j = 0; j < 2; ++j) {
                const int kk = wk * 16 + 8 * j + 2 * tq;
                float2 s2v = *(const float2*)(S2 + kk);
                float sbx = s2v.x * C1, sby = s2v.y * C1;
                float e0 = exp2f(fmaf(dl[j][0], 2.f * C1, -sbx));
                float e1 = exp2f(fmaf(dl[j][1], 2.f * C1, -sby));
                float e2 = exp2f(fmaf(dl[j][2], 2.f * C1, -sbx));
                float e3 = exp2f(fmaf(dl[j][3], 2.f * C1, -sby));
                float2 t01 = make_float2(tf32r(e0), tf32r(e1));
                float2 t23 = make_float2(tf32r(e2), tf32r(e3));
                *(float2*)(Et + (q0 + g) * ETP + kk)     = t01;
                *(float2*)(Et + (q0 + g + 8) * ETP + kk) = t23;
                pA += e0 + e1;
                pB += e2 + e3;
            }
            pA += __shfl_xor_sync(0xffffffffu, pA, 1);
            pA += __shfl_xor_sync(0xffffffffu, pA, 2);
            pB += __shfl_xor_sync(0xffffffffu, pB, 1);
            pB += __shfl_xor_sync(0xffffffffu, pB, 2);
            if (tq == 0) {
                atomicAdd(&Dn[q0 + g], pA);
                atomicAdd(&Dn[q0 + g + 8], pB);
            }
        }
        __syncthreads();   // Et complete

        // Readout MMA: D[32ch x 64q] += V[32ch x 64k] * Et^T (conflict-free frags)
        const uint32_t* Vu = (const uint32_t*)Vs;
        const uint32_t* Eu = (const uint32_t*)Et;
        #pragma unroll
        for (int s = 0; s < 8; ++s) {
            const int k0 = s * 8;
            uint32_t a[2][4];
            #pragma unroll
            for (int i = 0; i < 2; ++i) {
                int row = ch0 + 16 * i + g;
                a[i][0] = Vu[row * VP + k0 + tq];
                a[i][1] = Vu[(row + 8) * VP + k0 + tq];
                a[i][2] = Vu[row * VP + k0 + tq + 4];
                a[i][3] = Vu[(row + 8) * VP + k0 + tq + 4];
            }
            uint32_t bfr[8][2];
            #pragma unroll
            for (int j = 0; j < 8; ++j) {
                int q = j * 8 + g;
                bfr[j][0] = Eu[q * ETP + k0 + tq];
                bfr[j][1] = Eu[q * ETP + k0 + tq + 4];
            }
            #pragma unroll
            for (int i = 0; i < 2; ++i)
                #pragma unroll
                for (int j = 0; j < 8; ++j)
                    mma_tf32(d[i][j], a[i], bfr[j]);
        }
    }
    __syncthreads();
    if (tid < MQ) Dn[tid] = 1.0f / Dn[tid];
    __syncthreads();

    // Epilogue
    #pragma unroll
    for (int i = 0; i < 2; ++i) {
        int ch = ch0 + 16 * i + g;
        float* op0 = out + ((size_t)b * CVc + ch) * NPIX + m0;
        float* op1 = out + ((size_t)b * CVc + ch + 8) * NPIX + m0;
        #pragma unroll
        for (int j = 0; j < 8; ++j) {
            int q = j * 8 + 2 * tq;
            float2 dn2 = *(const float2*)(Dn + q);
            *(float2*)(op0 + q) = make_float2(d[i][j][0] * dn2.x, d[i][j][1] * dn2.y);
            *(float2*)(op1 + q) = make_float2(d[i][j][2] * dn2.x, d[i][j][3] * dn2.y);
        }
    }
}

extern "C" void kernel_launch(void* const* d_in, const int* in_sizes, int n_in,
                              void* d_out, int out_size)
{
    const float* mk = (const float*)d_in[0];
    const float* qk = (const float*)d_in[1];
    const float* mv = (const float*)d_in[2];
    const float* qv = (const float*)d_in[3];
    float* out = (float*)d_out;

    size_t smem = (size_t)SMEM_W * sizeof(float);   // 228864 B
    cudaFuncSetAttribute(mr_attn_kernel, cudaFuncAttributeMaxDynamicSharedMemorySize, (int)smem);

    dim3 grid(NPIX / MQ, Bsz);   // 49 x 16
    mr_attn_kernel<<<grid, THREADS, smem>>>(mk, qk, mv, out);

    size_t memElems = (size_t)Bsz * CVc * NPIX;
    if ((size_t)out_size >= 2 * memElems) {
        cudaMemcpyAsync(out + memElems, qv, memElems * sizeof(float),
                        cudaMemcpyDeviceToDevice);
    }
}

// round 11
// speedup vs baseline: 1.3184x; 1.1621x over previous
#include <cuda_runtime.h>
#include <cuda_bf16.h>
#include <cstdint>

// MemoryReader attention — tensor-pipe logits (bf16 3-split, m16n8k16) +
// tensor-pipe readout (tf32 m16n8k8), cp.async-overlapped V loads.
//   B=16, CK=64, CV=512, N=3136, 64 queries/CTA, 64-key tiles.
// R11: (a) logits via bf16 hi/lo split (hh+hl+lh), halving logit MMA slots and
// frag LDS vs 3xtf32; (b) V copied raw fp32 by cp.async.cg during the logit
// phase; readout MMA A-operand uses tf32 RZ-truncation of raw fp32 (adds
// ~2e-4 one-sided bias, total rel_err ~4-5e-4 < 1e-3).
// All frag/STS patterns bank-conflict-free (pitch 68: banks 4x+y bijective).

#define Bsz     16
#define CKc     64
#define CVc     512
#define NPIX    3136
#define MQ      64
#define NT      64
#define THREADS 512
#define NTILES  (NPIX / NT)   // 49
#define P       68            // universal pitch (words): %32==4

// smem word offsets
#define QBH_OFF 0                    // [32 cpair][64q] bf16x2 hi
#define QBL_OFF (QBH_OFF + 32 * P)   // lo
#define KBH_OFF (QBL_OFF + 32 * P)   // [32 cpair][64key] bf16x2 hi
#define KBL_OFF (KBH_OFF + 32 * P)   // lo
#define ET_OFF  (KBL_OFF + 32 * P)   // [64q][P] tf32 bits
#define VS_OFF  (ET_OFF + MQ * P)    // [512ch][P] raw fp32
#define S2_OFF  (VS_OFF + CVc * P)
#define DN_OFF  (S2_OFF + NT)
#define SMEM_W  (DN_OFF + MQ)        // 48000 words = 192000 B

__device__ __forceinline__ float tf32r(float x) {
    uint32_t u; asm("cvt.rna.tf32.f32 %0, %1;" : "=r"(u) : "f"(x));
    return __uint_as_float(u);
}
// pack: low16 = bf16(even), high16 = bf16(odd)
__device__ __forceinline__ uint32_t bf16x2p(float odd, float even) {
    uint32_t r;
    asm("cvt.rn.bf16x2.f32 %0, %1, %2;" : "=r"(r) : "f"(odd), "f"(even));
    return r;
}
__device__ __forceinline__ float bfLO(uint32_t w) { return __uint_as_float(w << 16); }
__device__ __forceinline__ float bfHI(uint32_t w) { return __uint_as_float(w & 0xffff0000u); }

__device__ __forceinline__ void mma_tf32(float d[4], const uint32_t a[4], const uint32_t b[2]) {
    asm volatile(
        "mma.sync.aligned.m16n8k8.row.col.f32.tf32.tf32.f32 "
        "{%0,%1,%2,%3}, {%4,%5,%6,%7}, {%8,%9}, {%0,%1,%2,%3};"
        : "+f"(d[0]), "+f"(d[1]), "+f"(d[2]), "+f"(d[3])
        : "r"(a[0]), "r"(a[1]), "r"(a[2]), "r"(a[3]), "r"(b[0]), "r"(b[1]));
}
__device__ __forceinline__ void mma_bf16(float d[4], const uint32_t a[4], const uint32_t b[2]) {
    asm volatile(
        "mma.sync.aligned.m16n8k16.row.col.f32.bf16.bf16.f32 "
        "{%0,%1,%2,%3}, {%4,%5,%6,%7}, {%8,%9}, {%0,%1,%2,%3};"
        : "+f"(d[0]), "+f"(d[1]), "+f"(d[2]), "+f"(d[3])
        : "r"(a[0]), "r"(a[1]), "r"(a[2]), "r"(a[3]), "r"(b[0]), "r"(b[1]));
}

__global__ __launch_bounds__(THREADS, 1)
void mr_attn_kernel(const float* __restrict__ mk, const float* __restrict__ qk,
                    const float* __restrict__ mv, float* __restrict__ out)
{
    extern __shared__ float sm[];
    float* Et = sm + ET_OFF;
    float* Vs = sm + VS_OFF;
    float* S2 = sm + S2_OFF;
    float* Dn = sm + DN_OFF;
    uint32_t* Qh = (uint32_t*)(sm + QBH_OFF);
    uint32_t* Ql = (uint32_t*)(sm + QBL_OFF);
    uint32_t* Kh = (uint32_t*)(sm + KBH_OFF);
    uint32_t* Kl = (uint32_t*)(sm + KBL_OFF);

    uint32_t sbase;
    asm("{ .reg .u64 t; cvta.to.shared.u64 t, %1; cvt.u32.u64 %0, t; }"
        : "=r"(sbase) : "l"(sm));

    const int b    = blockIdx.y;
    const int m0   = blockIdx.x * MQ;
    const int tid  = threadIdx.x;
    const int wid  = tid >> 5;
    const int lane = tid & 31;
    const int g    = lane >> 2;
    const int tq   = lane & 3;

    const float* qb = qk + (size_t)b * CKc * NPIX + m0;
    const float* kb = mk + (size_t)b * CKc * NPIX;
    const float* vb = mv + (size_t)b * CVc * NPIX;

    // Build Qb hi/lo bf16x2 ONCE: word (cpair, q) = {lo16: c=2cp, hi16: c=2cp+1}
    {
        int cp = tid >> 4, m4 = tid & 15;
        const float* q0p = qb + (2 * cp) * NPIX + 4 * m4;
        float4 qe = *(const float4*)(q0p);
        float4 qo = *(const float4*)(q0p + NPIX);
        float xe[4] = {qe.x, qe.y, qe.z, qe.w};
        float xo[4] = {qo.x, qo.y, qo.z, qo.w};
        uint32_t hv[4], lv[4];
        #pragma unroll
        for (int r = 0; r < 4; ++r) {
            uint32_t h = bf16x2p(xo[r], xe[r]);
            hv[r] = h;
            lv[r] = bf16x2p(xo[r] - bfHI(h), xe[r] - bfLO(h));
        }
        *(uint4*)(Qh + cp * P + 4 * m4) = *(uint4*)hv;
        *(uint4*)(Ql + cp * P + 4 * m4) = *(uint4*)lv;
    }
    if (tid < MQ) Dn[tid] = 0.f;

    // Readout accumulators: warp slab 32ch x 64q
    float d[2][8][4];
    #pragma unroll
    for (int i = 0; i < 2; ++i)
        #pragma unroll
        for (int j = 0; j < 8; ++j)
            #pragma unroll
            for (int r = 0; r < 4; ++r) d[i][j][r] = 0.f;

    const int ch0 = wid * 32;        // readout channel slab
    const int wq  = wid & 3;         // logit q m-tile (16q)
    const int wk  = wid >> 2;        // logit k n-pair (16k)
    const int q0  = wq * 16;

    for (int t = 0; t < NTILES; ++t) {
        const int n0 = t * NT;
        __syncthreads();   // prev readout done; Vs/Kb/Et reusable

        // V tile: cp.async raw fp32 GMEM -> SMEM (overlaps logit phase)
        #pragma unroll
        for (int i = 0; i < 16; ++i) {
            int idx = i * THREADS + tid;
            int c = idx >> 4, n4 = idx & 15;
            uint32_t dst = sbase + (uint32_t)(VS_OFF + c * P + 4 * n4) * 4u;
            const float* src = vb + c * NPIX + n0 + 4 * n4;
            asm volatile("cp.async.cg.shared.global [%0], [%1], 16;"
                         :: "r"(dst), "l"(src));
        }
        asm volatile("cp.async.commit_group;" ::: "memory");

        // K tile -> bf16 hi/lo packed pairs: word (cpair, key)
        {
            int cp = tid >> 4, n4 = tid & 15;
            const float* k0p = kb + (2 * cp) * NPIX + n0 + 4 * n4;
            float4 ke = *(const float4*)(k0p);
            float4 ko = *(const float4*)(k0p + NPIX);
            float xe[4] = {ke.x, ke.y, ke.z, ke.w};
            float xo[4] = {ko.x, ko.y, ko.z, ko.w};
            uint32_t hv[4], lv[4];
            #pragma unroll
            for (int r = 0; r < 4; ++r) {
                uint32_t h = bf16x2p(xo[r], xe[r]);
                hv[r] = h;
                lv[r] = bf16x2p(xo[r] - bfHI(h), xe[r] - bfLO(h));
            }
            *(uint4*)(Kh + cp * P + 4 * n4) = *(uint4*)hv;
            *(uint4*)(Kl + cp * P + 4 * n4) = *(uint4*)lv;
        }
        __syncthreads();   // Kb ready

        // ||k||^2 from bf16 hi+lo reconstruction (err ~2^-17, negligible)
        if (tid < NT) {
            float s = 0.f;
            #pragma unroll
            for (int cp = 0; cp < 32; ++cp) {
                uint32_t wh = Kh[cp * P + tid], wl = Kl[cp * P + tid];
                float ke = bfLO(wh) + bfLO(wl);
                float ko = bfHI(wh) + bfHI(wl);
                s = fmaf(ke, ke, fmaf(ko, ko, s));
            }
            S2[tid] = s;
        }

        // Logit MMA: 3x bf16-split (hh + hl + lh), 4 csteps of k16
        float dl[2][4] = {{0.f, 0.f, 0.f, 0.f}, {0.f, 0.f, 0.f, 0.f}};
        #pragma unroll
        for (int cs = 0; cs < 4; ++cs) {
            const int cb = cs * 8;   // cpair base
            uint32_t ah[4], al[4];
            ah[0] = Qh[(cb + tq) * P + q0 + g];
            ah[1] = Qh[(cb + tq) * P + q0 + g + 8];
            ah[2] = Qh[(cb + tq + 4) * P + q0 + g];
            ah[3] = Qh[(cb + tq + 4) * P + q0 + g + 8];
            al[0] = Ql[(cb + tq) * P + q0 + g];
            al[1] = Ql[(cb + tq) * P + q0 + g + 8];
            al[2] = Ql[(cb + tq + 4) * P + q0 + g];
            al[3] = Ql[(cb + tq + 4) * P + q0 + g + 8];
            #pragma unroll
            for (int j = 0; j < 2; ++j) {
                const int kk0 = wk * 16 + 8 * j;
                uint32_t bh[2], bl2[2];
                bh[0]  = Kh[(cb + tq) * P + kk0 + g];
                bh[1]  = Kh[(cb + tq + 4) * P + kk0 + g];
                bl2[0] = Kl[(cb + tq) * P + kk0 + g];
                bl2[1] = Kl[(cb + tq + 4) * P + kk0 + g];
                mma_bf16(dl[j], ah, bh);
                mma_bf16(dl[j], ah, bl2);
                mma_bf16(dl[j], al, bh);
            }
        }
        __syncthreads();   // S2 visible

        // exp + Et[q][k] (tf32 bits) + denominator
        {
            const float C1 = 0.125f * 1.4426950408889634f;   // log2(e)/8
            float pA = 0.f, pB = 0.f;
            #pragma unroll
            for (int j = 0; j < 2; ++j) {
                const int kk = wk * 16 + 8 * j + 2 * tq;
                float2 s2v = *(const float2*)(S2 + kk);
                float sbx = s2v.x * C1, sby = s2v.y * C1;
                float e0 = exp2f(fmaf(dl[j][0], 2.f * C1, -sbx));
                float e1 = exp2f(fmaf(dl[j][1], 2.f * C1, -sby));
                float e2 = exp2f(fmaf(dl[j][2], 2.f * C1, -sbx));
                float e3 = exp2f(fmaf(dl[j][3], 2.f * C1, -sby));
                *(float2*)(Et + (q0 + g) * P + kk)     = make_float2(tf32r(e0), tf32r(e1));
                *(float2*)(Et + (q0 + g + 8) * P + kk) = make_float2(tf32r(e2), tf32r(e3));
                pA += e0 + e1;
                pB += e2 + e3;
            }
            pA += __shfl_xor_sync(0xffffffffu, pA, 1);
            pA += __shfl_xor_sync(0xffffffffu, pA, 2);
            pB += __shfl_xor_sync(0xffffffffu, pB, 1);
            pB += __shfl_xor_sync(0xffffffffu, pB, 2);
            if (tq == 0) {
                atomicAdd(&Dn[q0 + g], pA);
                atomicAdd(&Dn[q0 + g + 8], pB);
            }
        }
        asm volatile("cp.async.wait_group 0;" ::: "memory");
        __syncthreads();   // Et + Vs ready

        // Readout MMA: D[32ch x 64q] += V[32ch x 64k] * Et^T (tf32; V raw fp32
        // bits -> HW RZ truncation). All frag patterns conflict-free.
        const uint32_t* Vu = (const uint32_t*)Vs;
        const uint32_t* Eu = (const uint32_t*)Et;
        #pragma unroll
        for (int s = 0; s < 8; ++s) {
            const int k0 = s * 8;
            uint32_t a[2][4];
            #pragma unroll
            for (int i = 0; i < 2; ++i) {
                int row = ch0 + 16 * i + g;
                a[i][0] = Vu[row * P + k0 + tq];
                a[i][1] = Vu[(row + 8) * P + k0 + tq];
                a[i][2] = Vu[row * P + k0 + tq + 4];
                a[i][3] = Vu[(row + 8) * P + k0 + tq + 4];
            }
            uint32_t bfr[8][2];
            #pragma unroll
            for (int j = 0; j < 8; ++j) {
                int q = j * 8 + g;
                bfr[j][0] = Eu[q * P + k0 + tq];
                bfr[j][1] = Eu[q * P + k0 + tq + 4];
            }
            #pragma unroll
            for (int i = 0; i < 2; ++i)
                #pragma unroll
                for (int j = 0; j < 8; ++j)
                    mma_tf32(d[i][j], a[i], bfr[j]);
        }
    }
    __syncthreads();
    if (tid < MQ) Dn[tid] = 1.0f / Dn[tid];
    __syncthreads();

    // Epilogue
    #pragma unroll
    for (int i = 0; i < 2; ++i) {
        int ch = ch0 + 16 * i + g;
        float* op0 = out + ((size_t)b * CVc + ch) * NPIX + m0;
        float* op1 = out + ((size_t)b * CVc + ch + 8) * NPIX + m0;
        #pragma unroll
        for (int j = 0; j < 8; ++j) {
            int q = j * 8 + 2 * tq;
            float2 dn2 = *(const float2*)(Dn + q);
            *(float2*)(op0 + q) = make_float2(d[i][j][0] * dn2.x, d[i][j][1] * dn2.y);
            *(float2*)(op1 + q) = make_float2(d[i][j][2] * dn2.x, d[i][j][3] * dn2.y);
        }
    }
}

extern "C" void kernel_launch(void* const* d_in, const int* in_sizes, int n_in,
                              void* d_out, int out_size)
{
    const float* mk = (const float*)d_in[0];
    const float* qk = (const float*)d_in[1];
    const float* mv = (const float*)d_in[2];
    const float* qv = (const float*)d_in[3];
    float* out = (float*)d_out;

    size_t smem = (size_t)SMEM_W * sizeof(float);   // 192000 B
    cudaFuncSetAttribute(mr_attn_kernel, cudaFuncAttributeMaxDynamicSharedMemorySize, (int)smem);

    dim3 grid(NPIX / MQ, Bsz);   // 49 x 16
    mr_attn_kernel<<<grid, THREADS, smem>>>(mk, qk, mv, out);

    size_t memElems = (size_t)Bsz * CVc * NPIX;
    if ((size_t)out_size >= 2 * memElems) {
        cudaMemcpyAsync(out + memElems, qv, memElems * sizeof(float),
                        cudaMemcpyDeviceToDevice);
    }
}

// round 12
// speedup vs baseline: 1.3328x; 1.0109x over previous
#include <cuda_runtime.h>
#include <cuda_bf16.h>
#include <cstdint>

// MemoryReader attention — tensor-pipe logits (bf16 3-split) + tf32 readout.
// R12: 2 CTAs/SM via channel split (blockIdx.z owns 256 of 512 V channels).
// Two resident CTAs overlap phases (one's logit/exp hides the other's readout).
// smem overlay: Et[64q][68] aliases the Kh|Kl region (K dead after logit MMA).
//   B=16, CK=64, CV=512, N=3136, 64 queries/CTA, 64-key tiles.

#define Bsz     16
#define CKc     64
#define CVc     512
#define NPIX    3136
#define MQ      64
#define NT      64
#define THREADS 256
#define NTILES  (NPIX / NT)   // 49
#define P       68            // universal pitch (words): %32==4
#define CVH     256           // channels per CTA

// smem word offsets (per CTA: 26240 words = 104960 B)
#define QBH_OFF 0                    // [32 cpair][P] bf16x2 hi (by q)
#define QBL_OFF (QBH_OFF + 32 * P)
#define KEH_OFF (QBL_OFF + 32 * P)   // Kh [32 cpair][P]  (Et overlays KEH..)
#define KEL_OFF (KEH_OFF + 32 * P)   // Kl
#define ET_OFF  KEH_OFF              // Et [64q][P] tf32 bits — OVERLAY
#define VS_OFF  (KEL_OFF + 32 * P)   // [256ch][P] raw fp32
#define S2_OFF  (VS_OFF + CVH * P)
#define DN_OFF  (S2_OFF + NT)
#define SMEM_W  (DN_OFF + MQ)        // 26240

__device__ __forceinline__ float tf32r(float x) {
    uint32_t u; asm("cvt.rna.tf32.f32 %0, %1;" : "=r"(u) : "f"(x));
    return __uint_as_float(u);
}
__device__ __forceinline__ uint32_t bf16x2p(float odd, float even) {
    uint32_t r;
    asm("cvt.rn.bf16x2.f32 %0, %1, %2;" : "=r"(r) : "f"(odd), "f"(even));
    return r;
}
__device__ __forceinline__ float bfLO(uint32_t w) { return __uint_as_float(w << 16); }
__device__ __forceinline__ float bfHI(uint32_t w) { return __uint_as_float(w & 0xffff0000u); }

__device__ __forceinline__ void mma_tf32(float d[4], const uint32_t a[4], const uint32_t b[2]) {
    asm volatile(
        "mma.sync.aligned.m16n8k8.row.col.f32.tf32.tf32.f32 "
        "{%0,%1,%2,%3}, {%4,%5,%6,%7}, {%8,%9}, {%0,%1,%2,%3};"
        : "+f"(d[0]), "+f"(d[1]), "+f"(d[2]), "+f"(d[3])
        : "r"(a[0]), "r"(a[1]), "r"(a[2]), "r"(a[3]), "r"(b[0]), "r"(b[1]));
}
__device__ __forceinline__ void mma_bf16(float d[4], const uint32_t a[4], const uint32_t b[2]) {
    asm volatile(
        "mma.sync.aligned.m16n8k16.row.col.f32.bf16.bf16.f32 "
        "{%0,%1,%2,%3}, {%4,%5,%6,%7}, {%8,%9}, {%0,%1,%2,%3};"
        : "+f"(d[0]), "+f"(d[1]), "+f"(d[2]), "+f"(d[3])
        : "r"(a[0]), "r"(a[1]), "r"(a[2]), "r"(a[3]), "r"(b[0]), "r"(b[1]));
}

__global__ __launch_bounds__(THREADS, 2)
void mr_attn_kernel(const float* __restrict__ mk, const float* __restrict__ qk,
                    const float* __restrict__ mv, float* __restrict__ out)
{
    extern __shared__ float sm[];
    float* Et = sm + ET_OFF;
    float* Vs = sm + VS_OFF;
    float* S2 = sm + S2_OFF;
    float* Dn = sm + DN_OFF;
    uint32_t* Qh = (uint32_t*)(sm + QBH_OFF);
    uint32_t* Ql = (uint32_t*)(sm + QBL_OFF);
    uint32_t* Kh = (uint32_t*)(sm + KEH_OFF);
    uint32_t* Kl = (uint32_t*)(sm + KEL_OFF);

    uint32_t sbase;
    asm("{ .reg .u64 t; cvta.to.shared.u64 t, %1; cvt.u32.u64 %0, t; }"
        : "=r"(sbase) : "l"(sm));

    const int b    = blockIdx.y;
    const int m0   = blockIdx.x * MQ;
    const int zc   = blockIdx.z * CVH;   // channel half base
    const int tid  = threadIdx.x;
    const int wid  = tid >> 5;           // 0..7
    const int lane = tid & 31;
    const int g    = lane >> 2;
    const int tq   = lane & 3;

    const float* qb = qk + (size_t)b * CKc * NPIX + m0;
    const float* kb = mk + (size_t)b * CKc * NPIX;
    const float* vb = mv + ((size_t)b * CVc + zc) * NPIX;

    // Build Qb hi/lo bf16x2 ONCE (512 slots, 2 iters)
    #pragma unroll
    for (int it = 0; it < 2; ++it) {
        int slot = it * THREADS + tid;
        int cp = slot >> 4, m4 = slot & 15;
        const float* q0p = qb + (2 * cp) * NPIX + 4 * m4;
        float4 qe = *(const float4*)(q0p);
        float4 qo = *(const float4*)(q0p + NPIX);
        float xe[4] = {qe.x, qe.y, qe.z, qe.w};
        float xo[4] = {qo.x, qo.y, qo.z, qo.w};
        uint32_t hv[4], lv[4];
        #pragma unroll
        for (int r = 0; r < 4; ++r) {
            uint32_t h = bf16x2p(xo[r], xe[r]);
            hv[r] = h;
            lv[r] = bf16x2p(xo[r] - bfHI(h), xe[r] - bfLO(h));
        }
        *(uint4*)(Qh + cp * P + 4 * m4) = *(uint4*)hv;
        *(uint4*)(Ql + cp * P + 4 * m4) = *(uint4*)lv;
    }
    if (tid < MQ) Dn[tid] = 0.f;

    // Readout accumulators: warp slab 32ch x 64q
    float d[2][8][4];
    #pragma unroll
    for (int i = 0; i < 2; ++i)
        #pragma unroll
        for (int j = 0; j < 8; ++j)
            #pragma unroll
            for (int r = 0; r < 4; ++r) d[i][j][r] = 0.f;

    const int ch0 = wid * 32;        // readout channel slab (within CTA half)
    const int wq  = wid & 3;         // logit q m-tile (16q)
    const int wk  = wid >> 2;        // logit k half (32k)
    const int q0  = wq * 16;
    const int kh0 = wk * 32;

    for (int t = 0; t < NTILES; ++t) {
        const int n0 = t * NT;
        __syncthreads();   // prev readout done; V/K(Et) reusable

        // V tile: cp.async raw fp32 (overlaps logit phase)
        #pragma unroll
        for (int i = 0; i < 16; ++i) {
            int idx = i * THREADS + tid;
            int c = idx >> 4, n4 = idx & 15;
            uint32_t dst = sbase + (uint32_t)(VS_OFF + c * P + 4 * n4) * 4u;
            const float* src = vb + c * NPIX + n0 + 4 * n4;
            asm volatile("cp.async.cg.shared.global [%0], [%1], 16;"
                         :: "r"(dst), "l"(src));
        }
        asm volatile("cp.async.commit_group;" ::: "memory");

        // K tile -> bf16 hi/lo packed cpairs (512 slots, 2 iters)
        #pragma unroll
        for (int it = 0; it < 2; ++it) {
            int slot = it * THREADS + tid;
            int cp = slot >> 4, n4 = slot & 15;
            const float* k0p = kb + (2 * cp) * NPIX + n0 + 4 * n4;
            float4 ke = *(const float4*)(k0p);
            float4 ko = *(const float4*)(k0p + NPIX);
            float xe[4] = {ke.x, ke.y, ke.z, ke.w};
            float xo[4] = {ko.x, ko.y, ko.z, ko.w};
            uint32_t hv[4], lv[4];
            #pragma unroll
            for (int r = 0; r < 4; ++r) {
                uint32_t h = bf16x2p(xo[r], xe[r]);
                hv[r] = h;
                lv[r] = bf16x2p(xo[r] - bfHI(h), xe[r] - bfLO(h));
            }
            *(uint4*)(Kh + cp * P + 4 * n4) = *(uint4*)hv;
            *(uint4*)(Kl + cp * P + 4 * n4) = *(uint4*)lv;
        }
        __syncthreads();   // Kb ready

        // ||k||^2 (warps 0-1)
        if (tid < NT) {
            float s = 0.f;
            #pragma unroll
            for (int cp = 0; cp < 32; ++cp) {
                uint32_t wh = Kh[cp * P + tid], wl = Kl[cp * P + tid];
                float ke = bfLO(wh) + bfLO(wl);
                float ko = bfHI(wh) + bfHI(wl);
                s = fmaf(ke, ke, fmaf(ko, ko, s));
            }
            S2[tid] = s;
        }

        // Logit MMA: warp = 16q x 32k, 3x bf16-split, 4 csteps of k16
        float dl[4][4];
        #pragma unroll
        for (int j = 0; j < 4; ++j)
            #pragma unroll
            for (int r = 0; r < 4; ++r) dl[j][r] = 0.f;
        #pragma unroll
        for (int cs = 0; cs < 4; ++cs) {
            const int cb = cs * 8;
            uint32_t ah[4], al[4];
            ah[0] = Qh[(cb + tq) * P + q0 + g];
            ah[1] = Qh[(cb + tq) * P + q0 + g + 8];
            ah[2] = Qh[(cb + tq + 4) * P + q0 + g];
            ah[3] = Qh[(cb + tq + 4) * P + q0 + g + 8];
            al[0] = Ql[(cb + tq) * P + q0 + g];
            al[1] = Ql[(cb + tq) * P + q0 + g + 8];
            al[2] = Ql[(cb + tq + 4) * P + q0 + g];
            al[3] = Ql[(cb + tq + 4) * P + q0 + g + 8];
            #pragma unroll
            for (int j = 0; j < 4; ++j) {
                const int kk0 = kh0 + 8 * j;
                uint32_t bh[2], bl2[2];
                bh[0]  = Kh[(cb + tq) * P + kk0 + g];
                bh[1]  = Kh[(cb + tq + 4) * P + kk0 + g];
                bl2[0] = Kl[(cb + tq) * P + kk0 + g];
                bl2[1] = Kl[(cb + tq + 4) * P + kk0 + g];
                mma_bf16(dl[j], ah, bh);
                mma_bf16(dl[j], ah, bl2);
                mma_bf16(dl[j], al, bh);
            }
        }
        __syncthreads();   // all K reads done (S2 + logit) -> Et may overlay

        // exp + Et[q][k] (tf32 bits, OVERLAYS K region) + denominator
        {
            const float C1 = 0.125f * 1.4426950408889634f;   // log2(e)/8
            float pA = 0.f, pB = 0.f;
            #pragma unroll
            for (int j = 0; j < 4; ++j) {
                const int kk = kh0 + 8 * j + 2 * tq;
                float2 s2v = *(const float2*)(S2 + kk);
                float sbx = s2v.x * C1, sby = s2v.y * C1;
                float e0 = exp2f(fmaf(dl[j][0], 2.f * C1, -sbx));
                float e1 = exp2f(fmaf(dl[j][1], 2.f * C1, -sby));
                float e2 = exp2f(fmaf(dl[j][2], 2.f * C1, -sbx));
                float e3 = exp2f(fmaf(dl[j][3], 2.f * C1, -sby));
                *(float2*)(Et + (q0 + g) * P + kk)     = make_float2(tf32r(e0), tf32r(e1));
                *(float2*)(Et + (q0 + g + 8) * P + kk) = make_float2(tf32r(e2), tf32r(e3));
                pA += e0 + e1;
                pB += e2 + e3;
            }
            pA += __shfl_xor_sync(0xffffffffu, pA, 1);
            pA += __shfl_xor_sync(0xffffffffu, pA, 2);
            pB += __shfl_xor_sync(0xffffffffu, pB, 1);
            pB += __shfl_xor_sync(0xffffffffu, pB, 2);
            if (tq == 0 && wk == 0) {   // one k-half reps per q after merge below
                // both k-halves contribute: wk==1 warps add separately
            }
            if (tq == 0) {
                atomicAdd(&Dn[q0 + g], pA);
                atomicAdd(&Dn[q0 + g + 8], pB);
            }
        }
        asm volatile("cp.async.wait_group 0;" ::: "memory");
        __syncthreads();   // Et + Vs ready

        // Readout MMA: D[32ch x 64q] += V * Et^T (tf32; V raw fp32 RZ-truncated)
        const uint32_t* Vu = (const uint32_t*)Vs;
        const uint32_t* Eu = (const uint32_t*)Et;
        #pragma unroll
        for (int s = 0; s < 8; ++s) {
            const int k0 = s * 8;
            uint32_t a[2][4];
            #pragma unroll
            for (int i = 0; i < 2; ++i) {
                int row = ch0 + 16 * i + g;
                a[i][0] = Vu[row * P + k0 + tq];
                a[i][1] = Vu[(row + 8) * P + k0 + tq];
                a[i][2] = Vu[row * P + k0 + tq + 4];
                a[i][3] = Vu[(row + 8) * P + k0 + tq + 4];
            }
            uint32_t bfr[8][2];
            #pragma unroll
            for (int j = 0; j < 8; ++j) {
                int q = j * 8 + g;
                bfr[j][0] = Eu[q * P + k0 + tq];
                bfr[j][1] = Eu[q * P + k0 + tq + 4];
            }
            #pragma unroll
            for (int i = 0; i < 2; ++i)
                #pragma unroll
                for (int j = 0; j < 8; ++j)
                    mma_tf32(d[i][j], a[i], bfr[j]);
        }
    }
    __syncthreads();
    if (tid < MQ) Dn[tid] = 1.0f / Dn[tid];
    __syncthreads();

    // Epilogue
    #pragma unroll
    for (int i = 0; i < 2; ++i) {
        int ch = zc + ch0 + 16 * i + g;
        float* op0 = out + ((size_t)b * CVc + ch) * NPIX + m0;
        float* op1 = out + ((size_t)b * CVc + ch + 8) * NPIX + m0;
        #pragma unroll
        for (int j = 0; j < 8; ++j) {
            int q = j * 8 + 2 * tq;
            float2 dn2 = *(const float2*)(Dn + q);
            *(float2*)(op0 + q) = make_float2(d[i][j][0] * dn2.x, d[i][j][1] * dn2.y);
            *(float2*)(op1 + q) = make_float2(d[i][j][2] * dn2.x, d[i][j][3] * dn2.y);
        }
    }
}

extern "C" void kernel_launch(void* const* d_in, const int* in_sizes, int n_in,
                              void* d_out, int out_size)
{
    const float* mk = (const float*)d_in[0];
    const float* qk = (const float*)d_in[1];
    const float* mv = (const float*)d_in[2];
    const float* qv = (const float*)d_in[3];
    float* out = (float*)d_out;

    size_t smem = (size_t)SMEM_W * sizeof(float);   // 104960 B
    cudaFuncSetAttribute(mr_attn_kernel, cudaFuncAttributeMaxDynamicSharedMemorySize, (int)smem);

    dim3 grid(NPIX / MQ, Bsz, 2);   // 49 x 16 x 2 (channel halves)
    mr_attn_kernel<<<grid, THREADS, smem>>>(mk, qk, mv, out);

    size_t memElems = (size_t)Bsz * CVc * NPIX;
    if ((size_t)out_size >= 2 * memElems) {
        cudaMemcpyAsync(out + memElems, qv, memElems * sizeof(float),
                        cudaMemcpyDeviceToDevice);
    }
}